// round 16
// baseline (speedup 1.0000x reference)
#include <cuda_runtime.h>
#include <math.h>

#define B   128
#define T_  400
#define KV  128
#define V_  1024
#define E_  256
#define H_  512
#define L_  300
#define NEG (-1e9f)

typedef unsigned long long u64;

// packed fp32x2 FMA: d.lo += a.lo*b.lo; d.hi += a.hi*b.hi  (exact fp32)
__device__ __forceinline__ void ffma2(u64 &d, u64 a, u64 b) {
    asm("fma.rn.f32x2 %0, %1, %2, %0;" : "+l"(d) : "l"(a), "l"(b));
}
__device__ __forceinline__ float lohi(u64 v) {
    float x, y;
    asm("mov.b64 {%0,%1}, %2;" : "=f"(x), "=f"(y) : "l"(v));
    return x + y;
}

// ---------------- persistent device state ----------------
__device__ float g_h1a[B * H_];
__device__ float g_h1b[B * H_];
__device__ float g_c1 [B * H_];
__device__ float g_h2x[2][B * KV];
__device__ float g_c2 [B * KV];
__device__ float g_ctx[B * KV];
__device__ float g_g2p[16 * B * 512];   // lstm2 partial gate sums [ht][b][gate]

// K-major transposed weights (float4 granularity):
__device__ float4 g_wt1[224 * 2048];    // rows permuted per-CTA (LSTM1)
__device__ float4 g_wt2[160 * 512];     // wt2[kc][gate], gate = src row identity
__device__ float4 g_wto[64 * 1024];

__device__ __forceinline__ float sigm(float x) { return 1.0f / (1.0f + expf(-x)); }

// ---------------- init ----------------
__global__ __launch_bounds__(256) void k_init() {
    int stride = gridDim.x * blockDim.x;
    int i0 = blockIdx.x * blockDim.x + threadIdx.x;
    for (int i = i0; i < B * H_; i += stride) { g_h1a[i] = 0.f; g_h1b[i] = 0.f; g_c1[i] = 0.f; }
    for (int i = i0; i < B * KV; i += stride) {
        g_h2x[0][i] = 0.f; g_h2x[1][i] = 0.f; g_c2[i] = 0.f; g_ctx[i] = 0.f;
    }
}

// ---------------- prep: build K-major transposed weights ----------------
#define N_WT1 (224 * 2048)
#define N_WT2 (160 * 512)
#define N_WTO (64 * 1024)
__global__ __launch_bounds__(256) void k_prep(
    const float* __restrict__ w_ih1, const float* __restrict__ w_hh1,
    const float* __restrict__ w_ih2, const float* __restrict__ w_hh2,
    const float* __restrict__ w_out)
{
    int idx = blockIdx.x * blockDim.x + threadIdx.x;
    if (idx < N_WT1) {
        int kc = idx >> 11, ri = idx & 2047;
        int htile = ri >> 7, loc = ri & 127;
        int g = loc >> 5, hl = loc & 31;
        int srow = g * H_ + htile * 32 + hl;
        int k = kc * 4;
        float4 v;
        if (k < 384) v = *(const float4*)(w_ih1 + (size_t)srow * 384 + k);
        else         v = *(const float4*)(w_hh1 + (size_t)srow * H_ + (k - 384));
        g_wt1[kc * 2048 + ri] = v;
    } else if (idx < N_WT1 + N_WT2) {
        int j = idx - N_WT1;
        int kc = j >> 9, ri = j & 511;       // ri = gate = source row (identity)
        int k = kc * 4;
        float4 v;
        if (k < 512) v = *(const float4*)(w_ih2 + (size_t)ri * H_ + k);
        else         v = *(const float4*)(w_hh2 + (size_t)ri * KV + (k - 512));
        g_wt2[kc * 512 + ri] = v;
    } else {
        int j = idx - N_WT1 - N_WT2;
        if (j < N_WTO) {
            int kc = j >> 10, r = j & 1023;
            g_wto[kc * 1024 + r] = *(const float4*)(w_out + (size_t)r * 256 + kc * 4);
        }
    }
}

// ---------------- logits: 16 CTAs x 512 threads, 512 v-rows x 16 b each, K=256 ----
__device__ __forceinline__ void logits_part(
    int c2, const float* __restrict__ b_out, float* __restrict__ out, int t)
{
    // logits for step tout = t-1 (t >= 1). h2(t-1) = g_h2x[(t+1)&1].
    __shared__ __align__(16) float xsl[16 * 260];
    const int tid = threadIdx.x;
    const int vt = c2 & 1, bt = c2 >> 1;
    const int v0 = vt * 512, b0 = bt * 16;
    const int tout = t - 1;
    const float* __restrict__ h2r = g_h2x[(t + 1) & 1];

    for (int e = tid; e < 16 * 256; e += 512) {
        int bb = e >> 8, kk = e & 255;
        float v = (kk < 128) ? h2r[(b0 + bb) * KV + kk]
                             : g_ctx[(b0 + bb) * KV + (kk - 128)];
        xsl[bb * 260 + kk] = v;
    }
    __syncthreads();

    const int rt = tid & 127, bh = tid >> 7;     // 4 batch-groups of 4
    u64 acc2[4][4];
#pragma unroll
    for (int j = 0; j < 4; j++)
#pragma unroll
        for (int jj = 0; jj < 4; jj++) acc2[j][jj] = 0ull;

    const ulonglong2* __restrict__ wb = (const ulonglong2*)g_wto;
    ulonglong2 wq[4][2];
#pragma unroll
    for (int p = 0; p < 2; p++)
#pragma unroll
        for (int j = 0; j < 4; j++)
            wq[j][p] = wb[p * 1024 + v0 + j * 128 + rt];

#pragma unroll 2
    for (int kc = 0; kc < 64; kc++) {
        ulonglong2 w[4];
#pragma unroll
        for (int j = 0; j < 4; j++) w[j] = wq[j][kc & 1];
        if (kc < 62) {
#pragma unroll
            for (int j = 0; j < 4; j++)
                wq[j][kc & 1] = wb[(kc + 2) * 1024 + v0 + j * 128 + rt];
        }
#pragma unroll
        for (int jj = 0; jj < 4; jj++) {
            ulonglong2 xv = *(const ulonglong2*)(xsl + (bh * 4 + jj) * 260 + kc * 4);
#pragma unroll
            for (int j = 0; j < 4; j++) {
                ffma2(acc2[j][jj], w[j].x, xv.x);
                ffma2(acc2[j][jj], w[j].y, xv.y);
            }
        }
    }

#pragma unroll
    for (int j = 0; j < 4; j++) {
        int r = v0 + j * 128 + rt;
        float bo = b_out[r];
#pragma unroll
        for (int jj = 0; jj < 4; jj++) {
            int b = b0 + bh * 4 + jj;
            __stcs(out + ((size_t)b * L_ + tout) * V_ + r, lohi(acc2[j][jj]) + bo);
        }
    }
}

// ---------------- kernel 1: LSTM1 + lstm2-partials on CTAs [0,128),
//                  logits(t-1) on [128,144); 512 threads.
// Double-buffered activation staging + one global weight ring over all 224 kc.
__global__ __launch_bounds__(512) void k_step1(
    const float* __restrict__ emb, const int* __restrict__ y,
    const float* __restrict__ b_ih1, const float* __restrict__ b_hh1,
    const float* __restrict__ b_out, float* __restrict__ out, int t)
{
    const int c = blockIdx.x, tid = threadIdx.x;
    if (c >= 128) {
        if (t > 0) logits_part(c - 128, b_out, out, t);
        return;
    }

    __shared__ __align__(16) float xs[2][16 * 132];
    __shared__ float gsm[128 * 17];
    __shared__ __align__(16) float h1s[16 * 36];   // h1_new tile [b][hh]
    __shared__ __align__(16) float h2s[16 * 8];    // old-h2 slice [b][8]
    __shared__ int toks[16];

    const int b0 = (c & 7) * 16, ht = c >> 3;
    const float* __restrict__ h1r = (t & 1) ? g_h1b : g_h1a;
    float* __restrict__       h1w = (t & 1) ? g_h1a : g_h1b;
    const float* __restrict__ h2r = g_h2x[(t + 1) & 1];   // old h2

    if (tid < 16) toks[tid] = (t == 0) ? 1 : y[(b0 + tid) * L_ + (t - 1)];
    __syncthreads();   // toks visible before any LDx

    const int row_t = tid & 127;      // g*32 + hl
    const int bh = tid >> 7;          // 4 batch-groups of 4
    const int ri = ht * 128 + row_t;
    const int sb = tid >> 7, sk = tid & 127;   // staging coords: 4 elems/thread

    float sreg[4];
    auto LDx = [&](int ch) {
#pragma unroll
        for (int j = 0; j < 4; j++) {
            int bb = sb + 4 * j;
            int k = ch * 128 + sk;
            float v;
            if (k < 256)      v = emb[(size_t)toks[bb] * E_ + k];
            else if (k < 384) v = g_ctx[(b0 + bb) * KV + (k - 256)];
            else              v = h1r[(size_t)(b0 + bb) * H_ + (k - 384)];
            sreg[j] = v;
        }
    };
    auto STx = [&](int buf) {
#pragma unroll
        for (int j = 0; j < 4; j++)
            xs[buf][(sb + 4 * j) * 132 + sk] = sreg[j];
    };

    u64 acc2[4];
#pragma unroll
    for (int j = 0; j < 4; j++) acc2[j] = 0ull;

    // global weight ring: contiguous over all 224 kc
    const ulonglong2* __restrict__ wp = (const ulonglong2*)(g_wt1 + ri);
    ulonglong2 wq[8];
#pragma unroll
    for (int p = 0; p < 8; p++) wq[p] = wp[(size_t)p * 2048];

    LDx(0); STx(0); __syncthreads();
#pragma unroll
    for (int ch = 0; ch < 7; ch++) {
        if (ch < 6) LDx(ch + 1);
        const float* __restrict__ xsb = xs[ch & 1];
#pragma unroll
        for (int kc = 0; kc < 32; kc++) {
            const int gk = ch * 32 + kc;       // global k-chunk (compile-time in body)
            ulonglong2 w = wq[kc & 7];
            if (gk < 216) wq[kc & 7] = wp[(size_t)(gk + 8) * 2048];
#pragma unroll
            for (int j = 0; j < 4; j++) {
                ulonglong2 xv = *(const ulonglong2*)(xsb + (bh * 4 + j) * 132 + kc * 4);
                ffma2(acc2[j], w.x, xv.x);
                ffma2(acc2[j], w.y, xv.y);
            }
        }
        if (ch < 6) STx((ch + 1) & 1);
        __syncthreads();
    }
#pragma unroll
    for (int j = 0; j < 4; j++) gsm[row_t * 17 + bh * 4 + j] = lohi(acc2[j]);

    // issue lstm2 weight loads NOW (independent of gsm): latency hides under
    // the MUFU-heavy pointwise below. Thread tid = gate in [0,512).
    ulonglong2 wv[10];
#pragma unroll
    for (int p = 0; p < 8; p++)
        wv[p] = *(const ulonglong2*)(g_wt2 + (size_t)(ht * 8 + p) * 512 + tid);
#pragma unroll
    for (int p = 0; p < 2; p++)
        wv[8 + p] = *(const ulonglong2*)(g_wt2 + (size_t)(128 + ht * 2 + p) * 512 + tid);

    // old-h2 slice for this CTA's lstm2 k-range: k in [512+ht*8, 512+ht*8+8)
    if (tid < 128) {
        int bb = tid >> 3, kk = tid & 7;
        h2s[bb * 8 + kk] = h2r[(b0 + bb) * KV + ht * 8 + kk];
    }
    __syncthreads();

    // pointwise: 32 h x 16 b = 512 cells, 1 per thread
    {
        int hh = tid & 31, bb = tid >> 5;
        int hidx = ht * 32 + hh;
        float gi = gsm[(0 * 32 + hh) * 17 + bb] + b_ih1[0 * H_ + hidx] + b_hh1[0 * H_ + hidx];
        float gf = gsm[(1 * 32 + hh) * 17 + bb] + b_ih1[1 * H_ + hidx] + b_hh1[1 * H_ + hidx];
        float gg = gsm[(2 * 32 + hh) * 17 + bb] + b_ih1[2 * H_ + hidx] + b_hh1[2 * H_ + hidx];
        float go = gsm[(3 * 32 + hh) * 17 + bb] + b_ih1[3 * H_ + hidx] + b_hh1[3 * H_ + hidx];
        int gidx = (b0 + bb) * H_ + hidx;
        float co = g_c1[gidx];
        float cn = sigm(gf) * co + sigm(gi) * tanhf(gg);
        g_c1[gidx] = cn;
        float h = sigm(go) * tanhf(cn);
        h1w[gidx] = h;
        h1s[bb * 36 + hh] = h;
    }
    __syncthreads();

    // lstm2 partial gates for this CTA's k-slice: h1[ht*32..+32) + h2_old[ht*8..+8)
    {
        float* __restrict__ gout = g_g2p + (size_t)ht * (B * 512);
#pragma unroll
        for (int b = 0; b < 16; b++) {
            const ulonglong2* xr = (const ulonglong2*)(h1s + b * 36);
            const ulonglong2* hr = (const ulonglong2*)(h2s + b * 8);
            u64 s = 0ull;
#pragma unroll
            for (int p = 0; p < 8; p++) {
                ulonglong2 xv = xr[p];
                ffma2(s, wv[p].x, xv.x);
                ffma2(s, wv[p].y, xv.y);
            }
            {
                ulonglong2 xv = hr[0];
                ffma2(s, wv[8].x, xv.x);
                ffma2(s, wv[8].y, xv.y);
                xv = hr[1];
                ffma2(s, wv[9].x, xv.x);
                ffma2(s, wv[9].y, xv.y);
            }
            gout[(size_t)(b0 + b) * 512 + tid] = lohi(s);
        }
    }
}

// ---------------- kernel 2: lstm2 finish + attention (1 CTA per b, 512 thr) ----------------
__global__ __launch_bounds__(512) void k_attn(
    const float* __restrict__ key, const float* __restrict__ val,
    const int* __restrict__ elen,
    const float* __restrict__ bi2, const float* __restrict__ bh2,
    float* __restrict__ out, int t)
{
    const int b = blockIdx.x, tid = threadIdx.x;
    const int lane = tid & 31, warp = tid >> 5;
    __shared__ __align__(16) float q[128];
    __shared__ float gates[512];
    __shared__ float a[T_];
    __shared__ float red[32];
    __shared__ float cred[3 * 128];

    // ---- lstm2 finish: reduce 16 partials + biases, pointwise ----
    {
        float gsum = 0.f;
#pragma unroll
        for (int ks = 0; ks < 16; ks++)
            gsum += g_g2p[(size_t)ks * (B * 512) + b * 512 + tid];
        gates[tid] = gsum + bi2[tid] + bh2[tid];
    }
    __syncthreads();
    if (tid < 128) {
        float gi = gates[tid], gf = gates[128 + tid];
        float gg = gates[256 + tid], go = gates[384 + tid];
        int idx = b * KV + tid;
        float co = g_c2[idx];
        float cn = sigm(gf) * co + sigm(gi) * tanhf(gg);
        g_c2[idx] = cn;
        float h = sigm(go) * tanhf(cn);
        g_h2x[t & 1][idx] = h;
        q[tid] = h;
    }
    __syncthreads();

    const int len = elen[b];

    // ---- energies: 4 threads per row; SKIP loads for rows >= len.
    //      row is uniform within each 4-lane quad, so the branch is
    //      quad-uniform and shuffles use a quad-local mask (safe).
    const int j4 = tid & 3, rb = tid >> 2;
    const unsigned qmask = 0xFu << (lane & ~3);
#pragma unroll
    for (int rr = 0; rr < 4; rr++) {
        int row = rb + rr * 128;
        if (row < len) {
            const ulonglong2* kr = (const ulonglong2*)(key + ((size_t)b * T_ + row) * KV);
            const ulonglong2* qv = (const ulonglong2*)q;
            u64 t2 = 0ull;
#pragma unroll
            for (int i = 0; i < 8; i++) {
                ulonglong2 kk = kr[j4 + 4 * i];
                ulonglong2 qq = qv[j4 + 4 * i];
                ffma2(t2, kk.x, qq.x);
                ffma2(t2, kk.y, qq.y);
            }
            float s = lohi(t2);
            s += __shfl_xor_sync(qmask, s, 1);
            s += __shfl_xor_sync(qmask, s, 2);
            if (j4 == 0) a[row] = s;
        } else if (j4 == 0 && row < T_) {
            a[row] = NEG;
        }
    }
    __syncthreads();

    // ---- max reduce ----
    float m = (tid < T_) ? a[tid] : -3.4e38f;
#pragma unroll
    for (int o = 16; o; o >>= 1) m = fmaxf(m, __shfl_xor_sync(0xffffffffu, m, o));
    if (lane == 0) red[warp] = m;
    __syncthreads();
    if (warp == 0) {
        float v = (lane < 16) ? red[lane] : -3.4e38f;
#pragma unroll
        for (int o = 16; o; o >>= 1) v = fmaxf(v, __shfl_xor_sync(0xffffffffu, v, o));
        if (lane == 0) red[0] = v;
    }
    __syncthreads();
    m = red[0];
    __syncthreads();

    // ---- exp + sum reduce (a[] keeps UNNORMALIZED p; normalization folded
    //      into plot write and context epilogue) ----
    float p = 0.f;
    if (tid < T_) { p = expf(a[tid] - m); a[tid] = p; }
    float s = p;
#pragma unroll
    for (int o = 16; o; o >>= 1) s += __shfl_xor_sync(0xffffffffu, s, o);
    if (lane == 0) red[warp] = s;
    __syncthreads();
    if (warp == 0) {
        float v = (lane < 16) ? red[lane] : 0.f;
#pragma unroll
        for (int o = 16; o; o >>= 1) v += __shfl_xor_sync(0xffffffffu, v, o);
        if (lane == 0) red[0] = v;
    }
    __syncthreads();
    const float inv = 1.0f / red[0];
    if (b == 0 && tid < T_)
        __stcs(out + (size_t)B * L_ * V_ + (size_t)t * T_ + tid, a[tid] * inv);

    // ---- context = (attn_unnorm @ value) * inv; rows interleaved by 4 so
    //      the 4 segments stay balanced for any len ----
    const int k = tid & 127, seg = tid >> 7;
    float acc = 0.f;
#pragma unroll 8
    for (int tt = seg; tt < len; tt += 4)
        acc += a[tt] * val[((size_t)b * T_ + tt) * KV + k];
    if (seg) cred[(seg - 1) * 128 + k] = acc;
    __syncthreads();
    if (seg == 0)
        g_ctx[b * KV + k] = (acc + cred[k] + cred[128 + k] + cred[256 + k]) * inv;
}

// ---------------- final logits for step L-1 ----------------
__global__ __launch_bounds__(512) void k_logits_fin(
    const float* __restrict__ b_out, float* __restrict__ out)
{
    logits_part(blockIdx.x, b_out, out, L_);   // tout = L_-1, h2 = g_h2x[(L_+1)&1]
}

// ---------------- launch ----------------
extern "C" void kernel_launch(void* const* d_in, const int* in_sizes, int n_in,
                              void* d_out, int out_size)
{
    const float* enc_key  = (const float*)d_in[0];
    const float* enc_val  = (const float*)d_in[1];
    const int*   elen     = (const int*)  d_in[2];
    const int*   y        = (const int*)  d_in[3];
    const float* emb      = (const float*)d_in[4];
    const float* w_ih1    = (const float*)d_in[5];
    const float* w_hh1    = (const float*)d_in[6];
    const float* b_ih1    = (const float*)d_in[7];
    const float* b_hh1    = (const float*)d_in[8];
    const float* w_ih2    = (const float*)d_in[9];
    const float* w_hh2    = (const float*)d_in[10];
    const float* b_ih2    = (const float*)d_in[11];
    const float* b_hh2    = (const float*)d_in[12];
    const float* w_out    = (const float*)d_in[13];
    const float* b_out    = (const float*)d_in[14];
    float* out = (float*)d_out;

    k_init<<<256, 256>>>();
    k_prep<<<(N_WT1 + N_WT2 + N_WTO + 255) / 256, 256>>>(w_ih1, w_hh1, w_ih2, w_hh2, w_out);
    for (int t = 0; t < L_; t++) {
        k_step1<<<144, 512>>>(emb, y, b_ih1, b_hh1, b_out, out, t);
        k_attn <<<B, 512>>>(enc_key, enc_val, elen, b_ih2, b_hh2, out, t);
    }
    k_logits_fin<<<16, 512>>>(b_out, out);
}

// round 17
// speedup vs baseline: 1.0468x; 1.0468x over previous
#include <cuda_runtime.h>
#include <math.h>

#define B   128
#define T_  400
#define KV  128
#define V_  1024
#define E_  256
#define H_  512
#define L_  300
#define NEG (-1e9f)

typedef unsigned long long u64;

// packed fp32x2 FMA: d.lo += a.lo*b.lo; d.hi += a.hi*b.hi  (exact fp32)
__device__ __forceinline__ void ffma2(u64 &d, u64 a, u64 b) {
    asm("fma.rn.f32x2 %0, %1, %2, %0;" : "+l"(d) : "l"(a), "l"(b));
}
__device__ __forceinline__ float lohi(u64 v) {
    float x, y;
    asm("mov.b64 {%0,%1}, %2;" : "=f"(x), "=f"(y) : "l"(v));
    return x + y;
}
// streaming (evict-first) 16B load: keeps the weight streams from evicting KV in L2
__device__ __forceinline__ ulonglong2 ldcs_u2(const ulonglong2* p) {
    ulonglong2 r;
    asm("ld.global.cs.v2.u64 {%0,%1}, [%2];" : "=l"(r.x), "=l"(r.y) : "l"(p));
    return r;
}

// ---------------- persistent device state ----------------
__device__ float g_h1a[B * H_];
__device__ float g_h1b[B * H_];
__device__ float g_c1 [B * H_];
__device__ float g_h2x[2][B * KV];
__device__ float g_c2 [B * KV];
__device__ float g_ctx[B * KV];
__device__ float g_g2p[16 * B * 512];   // lstm2 partial gate sums [ht][b][gate]

// K-major transposed weights (float4 granularity):
__device__ float4 g_wt1[224 * 2048];    // rows permuted per-CTA (LSTM1)
__device__ float4 g_wt2[160 * 512];     // wt2[kc][gate], gate = src row identity
__device__ float4 g_wto[64 * 1024];

__device__ __forceinline__ float sigm(float x) { return 1.0f / (1.0f + expf(-x)); }

// ---------------- init ----------------
__global__ __launch_bounds__(256) void k_init() {
    int stride = gridDim.x * blockDim.x;
    int i0 = blockIdx.x * blockDim.x + threadIdx.x;
    for (int i = i0; i < B * H_; i += stride) { g_h1a[i] = 0.f; g_h1b[i] = 0.f; g_c1[i] = 0.f; }
    for (int i = i0; i < B * KV; i += stride) {
        g_h2x[0][i] = 0.f; g_h2x[1][i] = 0.f; g_c2[i] = 0.f; g_ctx[i] = 0.f;
    }
}

// ---------------- prep: build K-major transposed weights ----------------
#define N_WT1 (224 * 2048)
#define N_WT2 (160 * 512)
#define N_WTO (64 * 1024)
__global__ __launch_bounds__(256) void k_prep(
    const float* __restrict__ w_ih1, const float* __restrict__ w_hh1,
    const float* __restrict__ w_ih2, const float* __restrict__ w_hh2,
    const float* __restrict__ w_out)
{
    int idx = blockIdx.x * blockDim.x + threadIdx.x;
    if (idx < N_WT1) {
        int kc = idx >> 11, ri = idx & 2047;
        int htile = ri >> 7, loc = ri & 127;
        int g = loc >> 5, hl = loc & 31;
        int srow = g * H_ + htile * 32 + hl;
        int k = kc * 4;
        float4 v;
        if (k < 384) v = *(const float4*)(w_ih1 + (size_t)srow * 384 + k);
        else         v = *(const float4*)(w_hh1 + (size_t)srow * H_ + (k - 384));
        g_wt1[kc * 2048 + ri] = v;
    } else if (idx < N_WT1 + N_WT2) {
        int j = idx - N_WT1;
        int kc = j >> 9, ri = j & 511;       // ri = gate = source row (identity)
        int k = kc * 4;
        float4 v;
        if (k < 512) v = *(const float4*)(w_ih2 + (size_t)ri * H_ + k);
        else         v = *(const float4*)(w_hh2 + (size_t)ri * KV + (k - 512));
        g_wt2[kc * 512 + ri] = v;
    } else {
        int j = idx - N_WT1 - N_WT2;
        if (j < N_WTO) {
            int kc = j >> 10, r = j & 1023;
            g_wto[kc * 1024 + r] = *(const float4*)(w_out + (size_t)r * 256 + kc * 4);
        }
    }
}

// ---------------- logits: 16 CTAs x 512 threads, 512 v-rows x 16 b each, K=256 ----
__device__ __forceinline__ void logits_part(
    int c2, const float* __restrict__ b_out, float* __restrict__ out, int t)
{
    // logits for step tout = t-1 (t >= 1). h2(t-1) = g_h2x[(t+1)&1].
    __shared__ __align__(16) float xsl[16 * 260];
    const int tid = threadIdx.x;
    const int vt = c2 & 1, bt = c2 >> 1;
    const int v0 = vt * 512, b0 = bt * 16;
    const int tout = t - 1;
    const float* __restrict__ h2r = g_h2x[(t + 1) & 1];

    for (int e = tid; e < 16 * 256; e += 512) {
        int bb = e >> 8, kk = e & 255;
        float v = (kk < 128) ? h2r[(b0 + bb) * KV + kk]
                             : g_ctx[(b0 + bb) * KV + (kk - 128)];
        xsl[bb * 260 + kk] = v;
    }
    __syncthreads();

    const int rt = tid & 127, bh = tid >> 7;     // 4 batch-groups of 4
    u64 acc2[4][4];
#pragma unroll
    for (int j = 0; j < 4; j++)
#pragma unroll
        for (int jj = 0; jj < 4; jj++) acc2[j][jj] = 0ull;

    const ulonglong2* __restrict__ wb = (const ulonglong2*)g_wto;
    ulonglong2 wq[4][2];
#pragma unroll
    for (int p = 0; p < 2; p++)
#pragma unroll
        for (int j = 0; j < 4; j++)
            wq[j][p] = ldcs_u2(wb + p * 1024 + v0 + j * 128 + rt);

#pragma unroll 2
    for (int kc = 0; kc < 64; kc++) {
        ulonglong2 w[4];
#pragma unroll
        for (int j = 0; j < 4; j++) w[j] = wq[j][kc & 1];
        if (kc < 62) {
#pragma unroll
            for (int j = 0; j < 4; j++)
                wq[j][kc & 1] = ldcs_u2(wb + (kc + 2) * 1024 + v0 + j * 128 + rt);
        }
#pragma unroll
        for (int jj = 0; jj < 4; jj++) {
            ulonglong2 xv = *(const ulonglong2*)(xsl + (bh * 4 + jj) * 260 + kc * 4);
#pragma unroll
            for (int j = 0; j < 4; j++) {
                ffma2(acc2[j][jj], w[j].x, xv.x);
                ffma2(acc2[j][jj], w[j].y, xv.y);
            }
        }
    }

#pragma unroll
    for (int j = 0; j < 4; j++) {
        int r = v0 + j * 128 + rt;
        float bo = b_out[r];
#pragma unroll
        for (int jj = 0; jj < 4; jj++) {
            int b = b0 + bh * 4 + jj;
            __stcs(out + ((size_t)b * L_ + tout) * V_ + r, lohi(acc2[j][jj]) + bo);
        }
    }
}

// ---------------- kernel 1: LSTM1 + lstm2-partials on CTAs [0,128),
//                  logits(t-1) on [128,144); 512 threads.
// Double-buffered activation staging + one global weight ring over all 224 kc.
// Weight streams use evict-first loads so enc_key/enc_value stay L2-resident.
__global__ __launch_bounds__(512) void k_step1(
    const float* __restrict__ emb, const int* __restrict__ y,
    const float* __restrict__ b_ih1, const float* __restrict__ b_hh1,
    const float* __restrict__ b_out, float* __restrict__ out, int t)
{
    const int c = blockIdx.x, tid = threadIdx.x;
    if (c >= 128) {
        if (t > 0) logits_part(c - 128, b_out, out, t);
        return;
    }

    __shared__ __align__(16) float xs[2][16 * 132];
    __shared__ float gsm[128 * 17];
    __shared__ __align__(16) float h1s[16 * 36];   // h1_new tile [b][hh]
    __shared__ __align__(16) float h2s[16 * 8];    // old-h2 slice [b][8]
    __shared__ int toks[16];

    const int b0 = (c & 7) * 16, ht = c >> 3;
    const float* __restrict__ h1r = (t & 1) ? g_h1b : g_h1a;
    float* __restrict__       h1w = (t & 1) ? g_h1a : g_h1b;
    const float* __restrict__ h2r = g_h2x[(t + 1) & 1];   // old h2

    if (tid < 16) toks[tid] = (t == 0) ? 1 : y[(b0 + tid) * L_ + (t - 1)];
    __syncthreads();   // toks visible before any LDx

    const int row_t = tid & 127;      // g*32 + hl
    const int bh = tid >> 7;          // 4 batch-groups of 4
    const int ri = ht * 128 + row_t;
    const int sb = tid >> 7, sk = tid & 127;   // staging coords: 4 elems/thread

    float sreg[4];
    auto LDx = [&](int ch) {
#pragma unroll
        for (int j = 0; j < 4; j++) {
            int bb = sb + 4 * j;
            int k = ch * 128 + sk;
            float v;
            if (k < 256)      v = emb[(size_t)toks[bb] * E_ + k];
            else if (k < 384) v = g_ctx[(b0 + bb) * KV + (k - 256)];
            else              v = h1r[(size_t)(b0 + bb) * H_ + (k - 384)];
            sreg[j] = v;
        }
    };
    auto STx = [&](int buf) {
#pragma unroll
        for (int j = 0; j < 4; j++)
            xs[buf][(sb + 4 * j) * 132 + sk] = sreg[j];
    };

    u64 acc2[4];
#pragma unroll
    for (int j = 0; j < 4; j++) acc2[j] = 0ull;

    // global weight ring: contiguous over all 224 kc, evict-first loads
    const ulonglong2* __restrict__ wp = (const ulonglong2*)(g_wt1 + ri);
    ulonglong2 wq[8];
#pragma unroll
    for (int p = 0; p < 8; p++) wq[p] = ldcs_u2(wp + (size_t)p * 2048);

    LDx(0); STx(0); __syncthreads();
#pragma unroll
    for (int ch = 0; ch < 7; ch++) {
        if (ch < 6) LDx(ch + 1);
        const float* __restrict__ xsb = xs[ch & 1];
#pragma unroll
        for (int kc = 0; kc < 32; kc++) {
            const int gk = ch * 32 + kc;       // global k-chunk (compile-time in body)
            ulonglong2 w = wq[kc & 7];
            if (gk < 216) wq[kc & 7] = ldcs_u2(wp + (size_t)(gk + 8) * 2048);
#pragma unroll
            for (int j = 0; j < 4; j++) {
                ulonglong2 xv = *(const ulonglong2*)(xsb + (bh * 4 + j) * 132 + kc * 4);
                ffma2(acc2[j], w.x, xv.x);
                ffma2(acc2[j], w.y, xv.y);
            }
        }
        if (ch < 6) STx((ch + 1) & 1);
        __syncthreads();
    }
#pragma unroll
    for (int j = 0; j < 4; j++) gsm[row_t * 17 + bh * 4 + j] = lohi(acc2[j]);

    // issue lstm2 weight loads NOW (independent of gsm): latency hides under
    // the MUFU-heavy pointwise below. Thread tid = gate in [0,512).
    ulonglong2 wv[10];
#pragma unroll
    for (int p = 0; p < 8; p++)
        wv[p] = ldcs_u2((const ulonglong2*)g_wt2 + (size_t)(ht * 8 + p) * 512 + tid);
#pragma unroll
    for (int p = 0; p < 2; p++)
        wv[8 + p] = ldcs_u2((const ulonglong2*)g_wt2 + (size_t)(128 + ht * 2 + p) * 512 + tid);

    // old-h2 slice for this CTA's lstm2 k-range: k in [512+ht*8, 512+ht*8+8)
    if (tid < 128) {
        int bb = tid >> 3, kk = tid & 7;
        h2s[bb * 8 + kk] = h2r[(b0 + bb) * KV + ht * 8 + kk];
    }
    __syncthreads();

    // pointwise: 32 h x 16 b = 512 cells, 1 per thread
    {
        int hh = tid & 31, bb = tid >> 5;
        int hidx = ht * 32 + hh;
        float gi = gsm[(0 * 32 + hh) * 17 + bb] + b_ih1[0 * H_ + hidx] + b_hh1[0 * H_ + hidx];
        float gf = gsm[(1 * 32 + hh) * 17 + bb] + b_ih1[1 * H_ + hidx] + b_hh1[1 * H_ + hidx];
        float gg = gsm[(2 * 32 + hh) * 17 + bb] + b_ih1[2 * H_ + hidx] + b_hh1[2 * H_ + hidx];
        float go = gsm[(3 * 32 + hh) * 17 + bb] + b_ih1[3 * H_ + hidx] + b_hh1[3 * H_ + hidx];
        int gidx = (b0 + bb) * H_ + hidx;
        float co = g_c1[gidx];
        float cn = sigm(gf) * co + sigm(gi) * tanhf(gg);
        g_c1[gidx] = cn;
        float h = sigm(go) * tanhf(cn);
        h1w[gidx] = h;
        h1s[bb * 36 + hh] = h;
    }
    __syncthreads();

    // lstm2 partial gates for this CTA's k-slice: h1[ht*32..+32) + h2_old[ht*8..+8)
    {
        float* __restrict__ gout = g_g2p + (size_t)ht * (B * 512);
#pragma unroll
        for (int b = 0; b < 16; b++) {
            const ulonglong2* xr = (const ulonglong2*)(h1s + b * 36);
            const ulonglong2* hr = (const ulonglong2*)(h2s + b * 8);
            u64 s = 0ull;
#pragma unroll
            for (int p = 0; p < 8; p++) {
                ulonglong2 xv = xr[p];
                ffma2(s, wv[p].x, xv.x);
                ffma2(s, wv[p].y, xv.y);
            }
            {
                ulonglong2 xv = hr[0];
                ffma2(s, wv[8].x, xv.x);
                ffma2(s, wv[8].y, xv.y);
                xv = hr[1];
                ffma2(s, wv[9].x, xv.x);
                ffma2(s, wv[9].y, xv.y);
            }
            __stcs(gout + (size_t)(b0 + b) * 512 + tid, lohi(s));
        }
    }
}

// ---------------- kernel 2: lstm2 finish + attention (1 CTA per b, 512 thr) ----------------
__global__ __launch_bounds__(512) void k_attn(
    const float* __restrict__ key, const float* __restrict__ val,
    const int* __restrict__ elen,
    const float* __restrict__ bi2, const float* __restrict__ bh2,
    float* __restrict__ out, int t)
{
    const int b = blockIdx.x, tid = threadIdx.x;
    const int lane = tid & 31, warp = tid >> 5;
    __shared__ __align__(16) float q[128];
    __shared__ float gates[512];
    __shared__ float a[T_];
    __shared__ float red[32];
    __shared__ float cred[3 * 128];

    // ---- lstm2 finish: reduce 16 partials + biases, pointwise ----
    {
        float gsum = 0.f;
#pragma unroll
        for (int ks = 0; ks < 16; ks++)
            gsum += __ldcs(g_g2p + (size_t)ks * (B * 512) + b * 512 + tid);
        gates[tid] = gsum + bi2[tid] + bh2[tid];
    }
    __syncthreads();
    if (tid < 128) {
        float gi = gates[tid], gf = gates[128 + tid];
        float gg = gates[256 + tid], go = gates[384 + tid];
        int idx = b * KV + tid;
        float co = g_c2[idx];
        float cn = sigm(gf) * co + sigm(gi) * tanhf(gg);
        g_c2[idx] = cn;
        float h = sigm(go) * tanhf(cn);
        g_h2x[t & 1][idx] = h;
        q[tid] = h;
    }
    __syncthreads();

    const int len = elen[b];

    // ---- energies: 4 threads per row, FFMA2, uniform shuffles ----
    const int j4 = tid & 3, rb = tid >> 2;
#pragma unroll
    for (int rr = 0; rr < 4; rr++) {
        int row = rb + rr * 128;
        int rowc = (row < T_) ? row : (T_ - 1);
        const ulonglong2* kr = (const ulonglong2*)(key + ((size_t)b * T_ + rowc) * KV);
        const ulonglong2* qv = (const ulonglong2*)q;
        u64 t2 = 0ull;
#pragma unroll
        for (int i = 0; i < 8; i++) {
            ulonglong2 kk = kr[j4 + 4 * i];
            ulonglong2 qq = qv[j4 + 4 * i];
            ffma2(t2, kk.x, qq.x);
            ffma2(t2, kk.y, qq.y);
        }
        float s = lohi(t2);
        s += __shfl_xor_sync(0xffffffffu, s, 1);
        s += __shfl_xor_sync(0xffffffffu, s, 2);
        if (j4 == 0 && row < T_) a[row] = (row < len) ? s : NEG;
    }
    __syncthreads();

    // ---- max reduce ----
    float m = (tid < T_) ? a[tid] : -3.4e38f;
#pragma unroll
    for (int o = 16; o; o >>= 1) m = fmaxf(m, __shfl_xor_sync(0xffffffffu, m, o));
    if (lane == 0) red[warp] = m;
    __syncthreads();
    if (warp == 0) {
        float v = (lane < 16) ? red[lane] : -3.4e38f;
#pragma unroll
        for (int o = 16; o; o >>= 1) v = fmaxf(v, __shfl_xor_sync(0xffffffffu, v, o));
        if (lane == 0) red[0] = v;
    }
    __syncthreads();
    m = red[0];
    __syncthreads();

    // ---- exp + sum reduce (a[] keeps UNNORMALIZED p; normalization folded
    //      into plot write and context epilogue) ----
    float p = 0.f;
    if (tid < T_) { p = expf(a[tid] - m); a[tid] = p; }
    float s = p;
#pragma unroll
    for (int o = 16; o; o >>= 1) s += __shfl_xor_sync(0xffffffffu, s, o);
    if (lane == 0) red[warp] = s;
    __syncthreads();
    if (warp == 0) {
        float v = (lane < 16) ? red[lane] : 0.f;
#pragma unroll
        for (int o = 16; o; o >>= 1) v += __shfl_xor_sync(0xffffffffu, v, o);
        if (lane == 0) red[0] = v;
    }
    __syncthreads();
    const float inv = 1.0f / red[0];
    if (b == 0 && tid < T_)
        __stcs(out + (size_t)B * L_ * V_ + (size_t)t * T_ + tid, a[tid] * inv);

    // ---- context = (attn_unnorm @ value) * inv over 4 row-segments of 100 ----
    const int k = tid & 127, seg = tid >> 7;
    float acc = 0.f;
    const int t0 = seg * 100;
    int t1 = t0 + 100; if (t1 > len) t1 = len;
#pragma unroll 8
    for (int tt = t0; tt < t1; tt++)
        acc += a[tt] * val[((size_t)b * T_ + tt) * KV + k];
    if (seg) cred[(seg - 1) * 128 + k] = acc;
    __syncthreads();
    if (seg == 0)
        g_ctx[b * KV + k] = (acc + cred[k] + cred[128 + k] + cred[256 + k]) * inv;
}

// ---------------- final logits for step L-1 ----------------
__global__ __launch_bounds__(512) void k_logits_fin(
    const float* __restrict__ b_out, float* __restrict__ out)
{
    logits_part(blockIdx.x, b_out, out, L_);   // tout = L_-1, h2 = g_h2x[(L_+1)&1]
}

// ---------------- launch ----------------
extern "C" void kernel_launch(void* const* d_in, const int* in_sizes, int n_in,
                              void* d_out, int out_size)
{
    const float* enc_key  = (const float*)d_in[0];
    const float* enc_val  = (const float*)d_in[1];
    const int*   elen     = (const int*)  d_in[2];
    const int*   y        = (const int*)  d_in[3];
    const float* emb      = (const float*)d_in[4];
    const float* w_ih1    = (const float*)d_in[5];
    const float* w_hh1    = (const float*)d_in[6];
    const float* b_ih1    = (const float*)d_in[7];
    const float* b_hh1    = (const float*)d_in[8];
    const float* w_ih2    = (const float*)d_in[9];
    const float* w_hh2    = (const float*)d_in[10];
    const float* b_ih2    = (const float*)d_in[11];
    const float* b_hh2    = (const float*)d_in[12];
    const float* w_out    = (const float*)d_in[13];
    const float* b_out    = (const float*)d_in[14];
    float* out = (float*)d_out;

    k_init<<<256, 256>>>();
    k_prep<<<(N_WT1 + N_WT2 + N_WTO + 255) / 256, 256>>>(w_ih1, w_hh1, w_ih2, w_hh2, w_out);
    for (int t = 0; t < L_; t++) {
        k_step1<<<144, 512>>>(emb, y, b_ih1, b_hh1, b_out, out, t);
        k_attn <<<B, 512>>>(enc_key, enc_val, elen, b_ih2, b_hh2, out, t);
    }
    k_logits_fin<<<16, 512>>>(b_out, out);
}